// round 12
// baseline (speedup 1.0000x reference)
#include <cuda_runtime.h>
#include <cstdint>

#define BATCH 16384
#define NN 32
#define NBLK (BATCH / 8)   // 2048 blocks, 4 warps, 2 matrices per warp

__device__ float        g_partial[3][NBLK];
__device__ unsigned int g_count = 0;

__device__ __forceinline__ float warp_sum(float x) {
#pragma unroll
    for (int o = 16; o > 0; o >>= 1) x += __shfl_xor_sync(0xffffffffu, x, o);
    return x;
}
// interleaved dual reductions: two independent chains overlap their SHFL latency
__device__ __forceinline__ void warp_sum2(float& x, float& y) {
#pragma unroll
    for (int o = 16; o > 0; o >>= 1) {
        float xs = __shfl_xor_sync(0xffffffffu, x, o);
        float ys = __shfl_xor_sync(0xffffffffu, y, o);
        x += xs; y += ys;
    }
}
__device__ __forceinline__ void warp_min2(float& x, float& y) {
#pragma unroll
    for (int o = 16; o > 0; o >>= 1) {
        float xs = __shfl_xor_sync(0xffffffffu, x, o);
        float ys = __shfl_xor_sync(0xffffffffu, y, o);
        x = fminf(x, xs); y = fminf(y, ys);
    }
}
__device__ __forceinline__ void warp_max2(float& x, float& y) {
#pragma unroll
    for (int o = 16; o > 0; o >>= 1) {
        float xs = __shfl_xor_sync(0xffffffffu, x, o);
        float ys = __shfl_xor_sync(0xffffffffu, y, o);
        x = fmaxf(x, xs); y = fmaxf(y, ys);
    }
}

// One warp handles TWO matrices (register-resident, lane = row) for intra-warp ILP.
__global__ __launch_bounds__(128) void fused_kernel(
    const float4* __restrict__ pred4, const float4* __restrict__ tgt4,
    const float*  __restrict__ mask,  float* __restrict__ out)
{
    __shared__ __align__(16) float s_tr[8][NN * 33];  // transpose / tridiag scratch per matrix slot
    __shared__ __align__(16) float s_v [8][NN];
    __shared__ __align__(16) float s_q [8][NN];
    __shared__ float s_red[8][3];
    __shared__ float s_fr[3][4];
    __shared__ bool  s_last;

    const int warp = threadIdx.x >> 5;
    const int lane = threadIdx.x & 31;
    const int slot0 = warp * 2, slot1 = warp * 2 + 1;
    const int b0 = (blockIdx.x << 3) + slot0;
    const int b1 = b0 + 1;

    float* tr0 = s_tr[slot0]; float* tr1 = s_tr[slot1];
    float* vb0 = s_v [slot0]; float* vb1 = s_v [slot1];
    float* qb0 = s_q [slot0]; float* qb1 = s_q [slot1];

    // ---- load both pred rows into registers ----
    float a[2][NN];
    {
        const float4* p0 = pred4 + (size_t)b0 * 256 + lane * 8;
        const float4* p1 = pred4 + (size_t)b1 * 256 + lane * 8;
#pragma unroll
        for (int j4 = 0; j4 < 8; j4++) {
            float4 v0 = p0[j4], v1 = p1[j4];
            a[0][4*j4+0] = v0.x; a[0][4*j4+1] = v0.y; a[0][4*j4+2] = v0.z; a[0][4*j4+3] = v0.w;
            a[1][4*j4+0] = v1.x; a[1][4*j4+1] = v1.y; a[1][4*j4+2] = v1.z; a[1][4*j4+3] = v1.w;
        }
    }
    float Dr0 = 0.f, Dr1 = 0.f;
#pragma unroll
    for (int j = 0; j < NN; j++) { Dr0 += a[0][j]; Dr1 += a[1][j]; }

    // stage rows to smem (33-pitch) for transpose + diag; masks staged in vb
    float m0 = mask[(b0 << 5) + lane];
    float m1 = mask[(b1 << 5) + lane];
    vb0[lane] = m0; vb1[lane] = m1;
#pragma unroll
    for (int j = 0; j < NN; j++) { tr0[lane * 33 + j] = a[0][j]; tr1[lane * 33 + j] = a[1][j]; }
    __syncwarp();

    // ---- BCE partials ----
    float sb0 = 0.f, sb1 = 0.f;
    {
        const float4* t0 = tgt4 + (size_t)b0 * 256 + lane * 8;
        const float4* t1 = tgt4 + (size_t)b1 * 256 + lane * 8;
        const float4* m40 = (const float4*)vb0;
        const float4* m41 = (const float4*)vb1;
#pragma unroll
        for (int j4 = 0; j4 < 8; j4++) {
            float4 t  = t0[j4]; float4 mm = m40[j4];
            float x0 = (t.x > 0.5f) ? a[0][4*j4+0] : 1.f - a[0][4*j4+0];
            float x1 = (t.y > 0.5f) ? a[0][4*j4+1] : 1.f - a[0][4*j4+1];
            float x2 = (t.z > 0.5f) ? a[0][4*j4+2] : 1.f - a[0][4*j4+2];
            float x3 = (t.w > 0.5f) ? a[0][4*j4+3] : 1.f - a[0][4*j4+3];
            sb0 += mm.x * (-__logf(x0)) + mm.y * (-__logf(x1))
                 + mm.z * (-__logf(x2)) + mm.w * (-__logf(x3));
            t = t1[j4]; mm = m41[j4];
            float y0 = (t.x > 0.5f) ? a[1][4*j4+0] : 1.f - a[1][4*j4+0];
            float y1 = (t.y > 0.5f) ? a[1][4*j4+1] : 1.f - a[1][4*j4+1];
            float y2 = (t.z > 0.5f) ? a[1][4*j4+2] : 1.f - a[1][4*j4+2];
            float y3 = (t.w > 0.5f) ? a[1][4*j4+3] : 1.f - a[1][4*j4+3];
            sb1 += mm.x * (-__logf(y0)) + mm.y * (-__logf(y1))
                 + mm.z * (-__logf(y2)) + mm.w * (-__logf(y3));
        }
        sb0 *= m0; sb1 *= m1;
    }
    warp_sum2(sb0, sb1);
    float c0 = m0, c1 = m1;
    warp_sum2(c0, c1);
    float smask0 = c0 * c0, smask1 = c1 * c1;

    // ---- build symmetrized Laplacians in registers ----
    const float jit = 1e-5f + (float)lane * (9.0e-5f / 31.0f);
    float dv0 = Dr0 + jit - tr0[lane * 33 + lane];
    float dv1 = Dr1 + jit - tr1[lane * 33 + lane];
#pragma unroll
    for (int j = 0; j < NN; j++) {
        float ct0 = tr0[j * 33 + lane];
        float ct1 = tr1[j * 33 + lane];
        a[0][j] = (j == lane) ? dv0 : -0.5f * (a[0][j] + ct0);
        a[1][j] = (j == lane) ? dv1 : -0.5f * (a[1][j] + ct1);
    }
    __syncwarp();   // mask reads done; vb reused for Householder v

    // ---- dual Householder tridiagonalization, fully unrolled ----
    float myd0 = 0.f, mye20 = 0.f, myd1 = 0.f, mye21 = 0.f;
#pragma unroll
    for (int k = 0; k < NN - 2; k++) {
        float x0 = a[0][k], x1v = a[1][k];
        float xi0 = (lane > k) ? x0 : 0.f;
        float xi1 = (lane > k) ? x1v : 0.f;
        float sg0 = xi0 * xi0, sg1 = xi1 * xi1;
        warp_sum2(sg0, sg1);
        float h0 = __shfl_sync(0xffffffffu, xi0, k + 1);
        float h1 = __shfl_sync(0xffffffffu, xi1, k + 1);
        float al0 = (h0 >= 0.f) ? -sqrtf(sg0) : sqrtf(sg0);
        float al1 = (h1 >= 0.f) ? -sqrtf(sg1) : sqrtf(sg1);
        if (lane == k) { myd0 = x0; mye20 = sg0; myd1 = x1v; mye21 = sg1; }

        float vi0 = (lane == (k + 1)) ? (h0 - al0) : xi0;
        float vi1 = (lane == (k + 1)) ? (h1 - al1) : xi1;
        float dn0 = sg0 - h0 * al0;
        float dn1 = sg1 - h1 * al1;
        float ta0 = (dn0 > 0.f) ? __fdividef(1.0f, dn0) : 0.f;
        float ta1 = (dn1 > 0.f) ? __fdividef(1.0f, dn1) : 0.f;
        vb0[lane] = vi0; vb1[lane] = vi1;
        __syncwarp();

        const float4* v40 = (const float4*)vb0;
        const float4* v41 = (const float4*)vb1;
        float pj0 = 0.f, pj1 = 0.f;
#pragma unroll
        for (int j4 = (k + 1) >> 2; j4 < 8; j4++) {
            float4 vv0 = v40[j4], vv1 = v41[j4];
            pj0 += a[0][4*j4+0]*vv0.x + a[0][4*j4+1]*vv0.y + a[0][4*j4+2]*vv0.z + a[0][4*j4+3]*vv0.w;
            pj1 += a[1][4*j4+0]*vv1.x + a[1][4*j4+1]*vv1.y + a[1][4*j4+2]*vv1.z + a[1][4*j4+3]*vv1.w;
        }
        pj0 = (lane > k) ? ta0 * pj0 : 0.f;
        pj1 = (lane > k) ? ta1 * pj1 : 0.f;
        float pv0 = pj0 * vi0, pv1 = pj1 * vi1;
        warp_sum2(pv0, pv1);
        float qj0 = fmaf(-0.5f * ta0 * pv0, vi0, pj0);
        float qj1 = fmaf(-0.5f * ta1 * pv1, vi1, pj1);
        qb0[lane] = qj0; qb1[lane] = qj1;
        __syncwarp();

        const float4* q40 = (const float4*)qb0;
        const float4* q41 = (const float4*)qb1;
#pragma unroll
        for (int j4 = (k + 1) >> 2; j4 < 8; j4++) {
            float4 vv0 = v40[j4], qq0 = q40[j4];
            float4 vv1 = v41[j4], qq1 = q41[j4];
            a[0][4*j4+0] = fmaf(-vi0, qq0.x, fmaf(-qj0, vv0.x, a[0][4*j4+0]));
            a[0][4*j4+1] = fmaf(-vi0, qq0.y, fmaf(-qj0, vv0.y, a[0][4*j4+1]));
            a[0][4*j4+2] = fmaf(-vi0, qq0.z, fmaf(-qj0, vv0.z, a[0][4*j4+2]));
            a[0][4*j4+3] = fmaf(-vi0, qq0.w, fmaf(-qj0, vv0.w, a[0][4*j4+3]));
            a[1][4*j4+0] = fmaf(-vi1, qq1.x, fmaf(-qj1, vv1.x, a[1][4*j4+0]));
            a[1][4*j4+1] = fmaf(-vi1, qq1.y, fmaf(-qj1, vv1.y, a[1][4*j4+1]));
            a[1][4*j4+2] = fmaf(-vi1, qq1.z, fmaf(-qj1, vv1.z, a[1][4*j4+2]));
            a[1][4*j4+3] = fmaf(-vi1, qq1.w, fmaf(-qj1, vv1.w, a[1][4*j4+3]));
        }
        __syncwarp();
    }
    if (lane == NN - 2) {
        myd0 = a[0][NN-2]; { float e = a[0][NN-1]; mye20 = e * e; }
        myd1 = a[1][NN-2]; { float e = a[1][NN-1]; mye21 = e * e; }
    }
    if (lane == NN - 1) {
        myd0 = a[0][NN-1]; mye20 = 0.f;
        myd1 = a[1][NN-1]; mye21 = 0.f;
    }

    // ---- publish tridiagonals, dual Sturm 33-section ----
    tr0[lane] = myd0; tr0[NN + lane] = mye20;
    tr1[lane] = myd1; tr1[NN + lane] = mye21;
    __syncwarp();

    float er0 = sqrtf(mye20), er1 = sqrtf(mye21);
    float ep0 = __shfl_up_sync(0xffffffffu, er0, 1);
    float ep1 = __shfl_up_sync(0xffffffffu, er1, 1);
    if (lane == 0) { ep0 = 0.f; ep1 = 0.f; }
    float lo0 = myd0 - (er0 + ep0), hi0 = myd0 + (er0 + ep0);
    float lo1 = myd1 - (er1 + ep1), hi1 = myd1 + (er1 + ep1);
    warp_min2(lo0, lo1);
    warp_max2(hi0, hi1);
    lo0 -= 1e-3f; lo1 -= 1e-3f; hi0 += 1e-3f; hi1 += 1e-3f;

    // 4 iterations: final width ~ 50/33^4 ~ 4e-5 absolute
    const float inv33 = 1.0f / 33.0f;
    for (int it = 0; it < 4; it++) {
        float w0 = hi0 - lo0, w1 = hi1 - lo1;
        float xx0 = fmaf(w0, (float)(lane + 1) * inv33, lo0);
        float xx1 = fmaf(w1, (float)(lane + 1) * inv33, lo1);
        int cnt0 = 0, cnt1 = 0;
        float q0 = tr0[0] - xx0, q1 = tr1[0] - xx1;
        cnt0 += (q0 < 0.f); cnt1 += (q1 < 0.f);
#pragma unroll
        for (int i = 1; i < NN; i++) {
            q0 = (q0 == 0.f) ? -1e-30f : q0;
            q1 = (q1 == 0.f) ? -1e-30f : q1;
            float d0 = tr0[i], e20 = tr0[NN + i - 1];
            float d1 = tr1[i], e21 = tr1[NN + i - 1];
            q0 = d0 - xx0 - __fdividef(e20, q0);
            q1 = d1 - xx1 - __fdividef(e21, q1);
            cnt0 += (q0 < 0.f); cnt1 += (q1 < 0.f);
        }
        unsigned mm0 = __ballot_sync(0xffffffffu, cnt0 >= 2);
        unsigned mm1 = __ballot_sync(0xffffffffu, cnt1 >= 2);
        if (mm0 == 0u) { lo0 = fmaf(w0, 32.0f * inv33, lo0); }
        else {
            int j = __ffs(mm0) - 1;
            hi0 = fmaf(w0, (float)(j + 1) * inv33, lo0);
            lo0 = (j == 0) ? lo0 : fmaf(w0, (float)j * inv33, lo0);
        }
        if (mm1 == 0u) { lo1 = fmaf(w1, 32.0f * inv33, lo1); }
        else {
            int j = __ffs(mm1) - 1;
            hi1 = fmaf(w1, (float)(j + 1) * inv33, lo1);
            lo1 = (j == 0) ? lo1 : fmaf(w1, (float)j * inv33, lo1);
        }
    }
    float lam0 = 0.5f * (lo0 + hi0);
    float lam1 = 0.5f * (lo1 + hi1);

    if (lane == 0) {
        out[2 + b0] = lam0;
        out[2 + b1] = lam1;
        s_red[slot0][0] = sb0; s_red[slot0][1] = smask0;
        s_red[slot0][2] = fmaxf(0.1f - lam0, 0.f);
        s_red[slot1][0] = sb1; s_red[slot1][1] = smask1;
        s_red[slot1][2] = fmaxf(0.1f - lam1, 0.f);
    }
    __syncthreads();

    // ---- grid-wide scalar reduction via last-block pattern ----
    if (threadIdx.x == 0) {
        float r0 = 0.f, r1 = 0.f, r2 = 0.f;
#pragma unroll
        for (int s = 0; s < 8; s++) { r0 += s_red[s][0]; r1 += s_red[s][1]; r2 += s_red[s][2]; }
        g_partial[0][blockIdx.x] = r0;
        g_partial[1][blockIdx.x] = r1;
        g_partial[2][blockIdx.x] = r2;
        __threadfence();
        unsigned v = atomicInc(&g_count, NBLK - 1);   // self-wrapping counter
        s_last = (v == NBLK - 1);
    }
    __syncthreads();

    if (s_last) {
        float r0 = 0.f, r1 = 0.f, r2 = 0.f;
        for (int i = threadIdx.x; i < NBLK; i += 128) {
            r0 += g_partial[0][i];
            r1 += g_partial[1][i];
            r2 += g_partial[2][i];
        }
        r0 = warp_sum(r0); r1 = warp_sum(r1); r2 = warp_sum(r2);
        int w2 = threadIdx.x >> 5, l2 = threadIdx.x & 31;
        if (l2 == 0) { s_fr[0][w2] = r0; s_fr[1][w2] = r1; s_fr[2][w2] = r2; }
        __syncthreads();
        if (threadIdx.x == 0) {
            float bb = s_fr[0][0] + s_fr[0][1] + s_fr[0][2] + s_fr[0][3];
            float mm = s_fr[1][0] + s_fr[1][1] + s_fr[1][2] + s_fr[1][3];
            float pp = s_fr[2][0] + s_fr[2][1] + s_fr[2][2] + s_fr[2][3];
            if (mm < 1.f) mm = 1.f;
            out[0] = bb / mm;
            out[1] = pp / (float)BATCH;
        }
    }
}

extern "C" void kernel_launch(void* const* d_in, const int* in_sizes, int n_in,
                              void* d_out, int out_size)
{
    const float* pred = (const float*)d_in[0];
    const float* tgt  = (const float*)d_in[1];
    const float* mask = (const float*)d_in[2];
    float* out = (float*)d_out;

    fused_kernel<<<NBLK, 128>>>((const float4*)pred, (const float4*)tgt, mask, out);
}

// round 15
// speedup vs baseline: 1.3348x; 1.3348x over previous
#include <cuda_runtime.h>
#include <cstdint>

#define BATCH 16384
#define NN 32
#define NBLK (BATCH / 4)   // 4096 blocks, 4 warps (matrices) each

__device__ float        g_partial[3][NBLK];   // planar: coalesced tail reduction
__device__ unsigned int g_count = 0;

__device__ __forceinline__ float warp_sum(float x) {
#pragma unroll
    for (int o = 16; o > 0; o >>= 1) x += __shfl_xor_sync(0xffffffffu, x, o);
    return x;
}
__device__ __forceinline__ float warp_min(float x) {
#pragma unroll
    for (int o = 16; o > 0; o >>= 1) x = fminf(x, __shfl_xor_sync(0xffffffffu, x, o));
    return x;
}
__device__ __forceinline__ float warp_max(float x) {
#pragma unroll
    for (int o = 16; o > 0; o >>= 1) x = fmaxf(x, __shfl_xor_sync(0xffffffffu, x, o));
    return x;
}

// One warp per matrix. Matrix lives in registers (lane = row).
// Natural register allocation (~80 regs): forcing 64 spills (R8), 2 matrices/warp
// kills occupancy (R12). This round shortens the per-step serial chain instead:
// the sigma reduction is overlapped with the A*x broadcast-dot, exploiting
// v == x except at component k+1 (fix-up: (Av)_j = dot_x - alpha*A[j][k+1]).
__global__ __launch_bounds__(128) void fused_kernel(
    const float4* __restrict__ pred4, const float4* __restrict__ tgt4,
    const float*  __restrict__ mask,  float* __restrict__ out)
{
    __shared__ __align__(16) float s_tr[4][NN * 33];  // transpose / tridiag scratch
    __shared__ __align__(16) float s_v [4][NN];
    __shared__ __align__(16) float s_q [4][NN];
    __shared__ float s_red[4][3];
    __shared__ float s_fr[3][4];
    __shared__ bool  s_last;

    const int warp = threadIdx.x >> 5;
    const int lane = threadIdx.x & 31;
    const int b    = (blockIdx.x << 2) + warp;

    float* tr = s_tr[warp];
    float* vb = s_v [warp];
    float* qb = s_q [warp];

    // ---- load own pred row into registers ----
    float a[NN];
    {
        const float4* prow = pred4 + (size_t)b * 256 + lane * 8;
#pragma unroll
        for (int j4 = 0; j4 < 8; j4++) {
            float4 v = prow[j4];
            a[4*j4+0] = v.x; a[4*j4+1] = v.y; a[4*j4+2] = v.z; a[4*j4+3] = v.w;
        }
    }
    float Dr = 0.f;
#pragma unroll
    for (int j = 0; j < NN; j++) Dr += a[j];

    // stage row to smem (33-pitch, conflict-free) for transpose + diag pick;
    // stage mask into vb for broadcast reads
    float m = mask[(b << 5) + lane];
    vb[lane] = m;
#pragma unroll
    for (int j = 0; j < NN; j++) tr[lane * 33 + j] = a[j];
    __syncwarp();

    // ---- BCE partial: row `lane`, tgt streamed, pred from regs ----
    float sb = 0.f;
    {
        const float4* trow = tgt4 + (size_t)b * 256 + lane * 8;
        const float4* m4   = (const float4*)vb;
#pragma unroll
        for (int j4 = 0; j4 < 8; j4++) {
            float4 t  = trow[j4];
            float4 mm = m4[j4];
            float p0 = a[4*j4+0], p1 = a[4*j4+1], p2 = a[4*j4+2], p3 = a[4*j4+3];
            float x0 = (t.x > 0.5f) ? p0 : 1.f - p0;
            float x1 = (t.y > 0.5f) ? p1 : 1.f - p1;
            float x2 = (t.z > 0.5f) ? p2 : 1.f - p2;
            float x3 = (t.w > 0.5f) ? p3 : 1.f - p3;
            sb += mm.x * (-__logf(x0)) + mm.y * (-__logf(x1))
                + mm.z * (-__logf(x2)) + mm.w * (-__logf(x3));
        }
        sb *= m;   // m_i factor for this row
    }
    sb = warp_sum(sb);
    float cntm  = warp_sum(m);
    float smask = cntm * cntm;

    // ---- build symmetrized Laplacian in registers ----
    const float jit  = 1e-5f + (float)lane * (9.0e-5f / 31.0f);
    float pii  = tr[lane * 33 + lane];
    float dval = Dr + jit - pii;
#pragma unroll
    for (int j = 0; j < NN; j++) {
        float c = tr[j * 33 + lane];                 // A[j][lane] (transpose)
        a[j] = (j == lane) ? dval : -0.5f * (a[j] + c);
    }
    __syncwarp();   // mask reads done; vb reused for Householder x/v

    // ---- Householder tridiagonalization, overlapped chain ----
    float myd = 0.f, mye2 = 0.f;
#pragma unroll
    for (int k = 0; k < NN - 2; k++) {
        float x  = a[k];                              // A[lane][k], const reg index
        float xi = (lane > k) ? x : 0.f;
        vb[lane] = xi;                                // publish RAW column x first
        __syncwarp();

        // These two are independent -> ptxas interleaves them:
        // (1) sigma butterfly, (2) partial broadcast-dot with x.
        float sigma = warp_sum(xi * xi);

        const float4* vb4 = (const float4*)vb;
        float pj = 0.f;
#pragma unroll
        for (int j4 = (k + 1) >> 2; j4 < 8; j4++) {   // vb zero below k+1
            float4 vv = vb4[j4];
            pj += a[4*j4+0] * vv.x + a[4*j4+1] * vv.y
                + a[4*j4+2] * vv.z + a[4*j4+3] * vv.w;
        }

        float x1 = __shfl_sync(0xffffffffu, xi, k + 1);
        float nrm   = sqrtf(sigma);
        float alpha = (x1 >= 0.f) ? -nrm : nrm;       // e[k]
        if (lane == k) { myd = x; mye2 = sigma; }     // d[k], e[k]^2

        float vi    = (lane == (k + 1)) ? (x1 - alpha) : xi;
        float denom = sigma - x1 * alpha;             // = v^T v / 2
        float tau   = (denom > 0.f) ? __fdividef(1.0f, denom) : 0.f;

        // fix-up: (A v)_j = dot_x - alpha * A[lane][k+1]
        pj = fmaf(-alpha, a[k + 1], pj);
        pj = (lane > k) ? tau * pj : 0.f;             // masked p = tau*A*v

        float pv = warp_sum(pj * vi);                 // shfl barrier: all dot reads done
        float qj = fmaf(-0.5f * tau * pv, vi, pj);
        qb[lane] = qj;
        if (lane == (k + 1)) vb[lane] = vi;           // patch x -> v (safe: post-butterfly)
        __syncwarp();

        const float4* qb4 = (const float4*)qb;
#pragma unroll
        for (int j4 = (k + 1) >> 2; j4 < 8; j4++) {
            float4 vv = vb4[j4];
            float4 qq = qb4[j4];
            a[4*j4+0] = fmaf(-vi, qq.x, fmaf(-qj, vv.x, a[4*j4+0]));
            a[4*j4+1] = fmaf(-vi, qq.y, fmaf(-qj, vv.y, a[4*j4+1]));
            a[4*j4+2] = fmaf(-vi, qq.z, fmaf(-qj, vv.z, a[4*j4+2]));
            a[4*j4+3] = fmaf(-vi, qq.w, fmaf(-qj, vv.w, a[4*j4+3]));
        }
        __syncwarp();   // before next iteration's vb overwrite
    }
    if (lane == NN - 2) {
        myd = a[NN - 2];
        float e = a[NN - 1];
        mye2 = e * e;
    }
    if (lane == NN - 1) { myd = a[NN - 1]; mye2 = 0.f; }

    // ---- publish tridiagonal, Sturm 33-section for lambda_2 ----
    tr[lane]      = myd;
    tr[NN + lane] = mye2;
    __syncwarp();

    float er  = sqrtf(mye2);
    float erp = __shfl_up_sync(0xffffffffu, er, 1);
    if (lane == 0) erp = 0.f;
    float rad = er + erp;
    float lo = warp_min(myd - rad) - 1e-3f;
    float hi = warp_max(myd + rad) + 1e-3f;

    // 4 iterations: width ~ 50/33^4 ~ 4e-5 absolute, ~100x inside the 1e-3 gate
    const float inv33 = 1.0f / 33.0f;
    for (int it = 0; it < 4; it++) {
        float w = hi - lo;
        float xx = fmaf(w, (float)(lane + 1) * inv33, lo);
        int cnt = 0;
        float q = tr[0] - xx;
        cnt += (q < 0.f);
#pragma unroll
        for (int i = 1; i < NN; i++) {
            if (q == 0.f) q = -1e-30f;
            q = tr[i] - xx - __fdividef(tr[NN + i - 1], q);
            cnt += (q < 0.f);
        }
        unsigned mm = __ballot_sync(0xffffffffu, cnt >= 2);
        if (mm == 0u) {
            lo = fmaf(w, 32.0f * inv33, lo);
        } else {
            int j = __ffs(mm) - 1;
            float nhi = fmaf(w, (float)(j + 1) * inv33, lo);
            float nlo = (j == 0) ? lo : fmaf(w, (float)j * inv33, lo);
            hi = nhi; lo = nlo;
        }
    }
    float lam2 = 0.5f * (lo + hi);

    if (lane == 0) {
        out[2 + b] = lam2;
        s_red[warp][0] = sb;
        s_red[warp][1] = smask;
        s_red[warp][2] = fmaxf(0.1f - lam2, 0.f);
    }
    __syncthreads();

    // ---- grid-wide scalar reduction via last-block pattern ----
    if (threadIdx.x == 0) {
        g_partial[0][blockIdx.x] = s_red[0][0] + s_red[1][0] + s_red[2][0] + s_red[3][0];
        g_partial[1][blockIdx.x] = s_red[0][1] + s_red[1][1] + s_red[2][1] + s_red[3][1];
        g_partial[2][blockIdx.x] = s_red[0][2] + s_red[1][2] + s_red[2][2] + s_red[3][2];
        __threadfence();
        unsigned v = atomicInc(&g_count, NBLK - 1);   // self-wrapping counter
        s_last = (v == NBLK - 1);
    }
    __syncthreads();

    if (s_last) {
        float r0 = 0.f, r1 = 0.f, r2 = 0.f;
        for (int i = threadIdx.x; i < NBLK; i += 128) {   // coalesced planar reads
            r0 += g_partial[0][i];
            r1 += g_partial[1][i];
            r2 += g_partial[2][i];
        }
        r0 = warp_sum(r0); r1 = warp_sum(r1); r2 = warp_sum(r2);
        int w2 = threadIdx.x >> 5, l2 = threadIdx.x & 31;
        if (l2 == 0) { s_fr[0][w2] = r0; s_fr[1][w2] = r1; s_fr[2][w2] = r2; }
        __syncthreads();
        if (threadIdx.x == 0) {
            float b0 = s_fr[0][0] + s_fr[0][1] + s_fr[0][2] + s_fr[0][3];
            float m0 = s_fr[1][0] + s_fr[1][1] + s_fr[1][2] + s_fr[1][3];
            float p0 = s_fr[2][0] + s_fr[2][1] + s_fr[2][2] + s_fr[2][3];
            if (m0 < 1.f) m0 = 1.f;
            out[0] = b0 / m0;
            out[1] = p0 / (float)BATCH;
        }
    }
}

extern "C" void kernel_launch(void* const* d_in, const int* in_sizes, int n_in,
                              void* d_out, int out_size)
{
    const float* pred = (const float*)d_in[0];
    const float* tgt  = (const float*)d_in[1];
    const float* mask = (const float*)d_in[2];
    float* out = (float*)d_out;

    fused_kernel<<<NBLK, 128>>>((const float4*)pred, (const float4*)tgt, mask, out);
}